// round 4
// baseline (speedup 1.0000x reference)
#include <cuda_runtime.h>
#include <cuda_bf16.h>
#include <math.h>

// ---------------------------------------------------------------------------
// Problem constants
// ---------------------------------------------------------------------------
#define BATCH   32
#define NTOK    255
#define NTOT    256
#define DIN     64
#define NHEAD   12
#define HID     768
#define FFN     3072
#define NLAYER  6
#define HDIM    64
#define MROWS   (BATCH*NTOT) // 8192
#define MATOM   (BATCH*NTOK) // 8160

// ---------------------------------------------------------------------------
// Scratch (device globals; no allocations allowed)
// ---------------------------------------------------------------------------
__device__ __align__(256) float g_h  [(size_t)MROWS*HID];
__device__ __align__(256) float g_y  [(size_t)MROWS*HID];
__device__ __align__(256) float g_q  [(size_t)MROWS*HID];
__device__ __align__(256) float g_k  [(size_t)MROWS*HID];
__device__ __align__(256) float g_v  [(size_t)MROWS*HID];
__device__ __align__(256) float g_o  [(size_t)MROWS*HID];
__device__ __align__(256) float g_f  [(size_t)MROWS*FFN];
__device__ __align__(256) float g_bias[(size_t)BATCH*NHEAD*NTOT*NTOT];

enum { EP_BIAS = 0, EP_BIAS_RES = 1, EP_BIAS_GELU = 2 };

// ---------------------------------------------------------------------------
// fp32 SGEMM (kept only for the small atom-encoder GEMM, K=64, with row remap)
// ---------------------------------------------------------------------------
#define BM 128
#define BN 128
#define BK 8
#define TM 8
#define TN 8

template<int MODE, bool REMAP>
__global__ __launch_bounds__(256) void sgemm_kernel(
    const float* __restrict__ A, const float* __restrict__ W,
    const float* __restrict__ bias, const float* __restrict__ R,
    float* __restrict__ C, int M, int K, int N)
{
    __shared__ float As[BK][BM];
    __shared__ float Bs[BK][BN];

    const int tid = threadIdx.x;
    const int bm0 = blockIdx.y * BM;
    const int bn0 = blockIdx.x * BN;
    const int tx = tid & 15;
    const int ty = tid >> 4;

    float acc[TM][TN];
    #pragma unroll
    for (int i = 0; i < TM; i++)
        #pragma unroll
        for (int j = 0; j < TN; j++) acc[i][j] = 0.f;

    const int arow = tid >> 1;
    const int acol = (tid & 1) * 4;
    const int brow = tid >> 5;
    const int bcol = (tid & 31) * 4;

    for (int k0 = 0; k0 < K; k0 += BK) {
        float4 av;
        const int gm = bm0 + arow;
        if (gm < M)
            av = *reinterpret_cast<const float4*>(A + (size_t)gm * K + k0 + acol);
        else
            av = make_float4(0.f, 0.f, 0.f, 0.f);
        As[acol + 0][arow] = av.x;
        As[acol + 1][arow] = av.y;
        As[acol + 2][arow] = av.z;
        As[acol + 3][arow] = av.w;

        const float4 bv = *reinterpret_cast<const float4*>(
            W + (size_t)(k0 + brow) * N + bn0 + bcol);
        *reinterpret_cast<float4*>(&Bs[brow][bcol]) = bv;

        __syncthreads();
        #pragma unroll
        for (int k = 0; k < BK; k++) {
            float af[TM], bf[TN];
            #pragma unroll
            for (int i = 0; i < TM; i++) af[i] = As[k][ty * TM + i];
            #pragma unroll
            for (int j = 0; j < TN; j++) bf[j] = Bs[k][tx * TN + j];
            #pragma unroll
            for (int i = 0; i < TM; i++)
                #pragma unroll
                for (int j = 0; j < TN; j++)
                    acc[i][j] = fmaf(af[i], bf[j], acc[i][j]);
        }
        __syncthreads();
    }

    #pragma unroll
    for (int i = 0; i < TM; i++) {
        const int m = bm0 + ty * TM + i;
        if (m >= M) continue;
        size_t orow;
        if (REMAP) orow = (size_t)m + (size_t)(m / NTOK) * 1 + 1;
        else       orow = (size_t)m;
        #pragma unroll
        for (int j = 0; j < TN; j++) {
            const int nn = bn0 + tx * TN + j;
            float v = acc[i][j] + bias[nn];
            if (MODE == EP_BIAS_GELU)
                v = 0.5f * v * (1.f + erff(v * 0.70710678118654752f));
            if (MODE == EP_BIAS_RES)
                v += R[orow * N + nn];
            C[orow * N + nn] = v;
        }
    }
}

// ---------------------------------------------------------------------------
// Tensor-core TF32 GEMM, double-buffered + register-prefetch pipeline.
// CTA tile 128x128x16, 8 warps (4 along M, 2 along N), warp tile 32x64,
// mma.sync.m16n8k8.tf32, fp32 accumulate. M,N,K multiples of tile sizes.
// ---------------------------------------------------------------------------
#define XBM 128
#define XBN 128
#define XBK 16
#define XPAD 8
#define XLDA (XBM + XPAD)   // 136
#define XLDB (XBN + XPAD)   // 136

__device__ __forceinline__ unsigned f2tf32(float f) {
    unsigned u;
    asm("cvt.rna.tf32.f32 %0, %1;" : "=r"(u) : "f"(f));
    return u;
}

__device__ __forceinline__ void mma16n8k8(float c[4], const unsigned a[4],
                                          const unsigned b[2]) {
    asm volatile(
        "mma.sync.aligned.m16n8k8.row.col.f32.tf32.tf32.f32 "
        "{%0,%1,%2,%3}, {%4,%5,%6,%7}, {%8,%9}, {%0,%1,%2,%3};"
        : "+f"(c[0]), "+f"(c[1]), "+f"(c[2]), "+f"(c[3])
        : "r"(a[0]), "r"(a[1]), "r"(a[2]), "r"(a[3]), "r"(b[0]), "r"(b[1]));
}

template<int MODE>
__global__ __launch_bounds__(256, 2) void tgemm_kernel(
    const float* __restrict__ A, const float* __restrict__ W,
    const float* __restrict__ bias, const float* __restrict__ R,
    float* __restrict__ C, int M, int K, int N)
{
    __shared__ unsigned As[2][XBK][XLDA];
    __shared__ unsigned Bs[2][XBK][XLDB];

    const int tid  = threadIdx.x;
    const int lane = tid & 31;
    const int warp = tid >> 5;
    const int g    = lane >> 2;   // 0..7
    const int q    = lane & 3;    // 0..3

    const int bm0 = blockIdx.y * XBM;
    const int bn0 = blockIdx.x * XBN;
    const int wm  = (warp >> 1) * 32;
    const int wn  = (warp & 1) * 64;

    // loader indices
    const int arow  = tid >> 1;           // 0..127
    const int acol0 = (tid & 1) * 8;      // 0 or 8
    const int brow  = tid >> 4;           // 0..15
    const int bcol0 = (tid & 15) * 8;     // 0..120

    float acc[2][8][4];
    #pragma unroll
    for (int t = 0; t < 2; t++)
        #pragma unroll
        for (int j = 0; j < 8; j++)
            #pragma unroll
            for (int r = 0; r < 4; r++) acc[t][j][r] = 0.f;

    const float* Aptr = A + (size_t)(bm0 + arow) * K + acol0;
    const float* Wptr = W + (size_t)brow * N + bn0 + bcol0;

    // ---- prologue: tile 0 -> smem buf 0 ----
    {
        const float4 a0 = *reinterpret_cast<const float4*>(Aptr);
        const float4 a1 = *reinterpret_cast<const float4*>(Aptr + 4);
        As[0][acol0 + 0][arow] = f2tf32(a0.x);
        As[0][acol0 + 1][arow] = f2tf32(a0.y);
        As[0][acol0 + 2][arow] = f2tf32(a0.z);
        As[0][acol0 + 3][arow] = f2tf32(a0.w);
        As[0][acol0 + 4][arow] = f2tf32(a1.x);
        As[0][acol0 + 5][arow] = f2tf32(a1.y);
        As[0][acol0 + 6][arow] = f2tf32(a1.z);
        As[0][acol0 + 7][arow] = f2tf32(a1.w);

        const float4 b0 = *reinterpret_cast<const float4*>(Wptr);
        const float4 b1 = *reinterpret_cast<const float4*>(Wptr + 4);
        uint4 u0, u1;
        u0.x = f2tf32(b0.x); u0.y = f2tf32(b0.y);
        u0.z = f2tf32(b0.z); u0.w = f2tf32(b0.w);
        u1.x = f2tf32(b1.x); u1.y = f2tf32(b1.y);
        u1.z = f2tf32(b1.z); u1.w = f2tf32(b1.w);
        *reinterpret_cast<uint4*>(&Bs[0][brow][bcol0])     = u0;
        *reinterpret_cast<uint4*>(&Bs[0][brow][bcol0 + 4]) = u1;
    }
    __syncthreads();

    int buf = 0;
    for (int k0 = 0; k0 < K; k0 += XBK) {
        const bool more = (k0 + XBK) < K;

        // ---- prefetch next tile into registers (LDG issued before compute) ----
        float4 na0, na1, nb0, nb1;
        if (more) {
            na0 = *reinterpret_cast<const float4*>(Aptr + k0 + XBK);
            na1 = *reinterpret_cast<const float4*>(Aptr + k0 + XBK + 4);
            const float* wp = Wptr + (size_t)(k0 + XBK) * N;
            nb0 = *reinterpret_cast<const float4*>(wp);
            nb1 = *reinterpret_cast<const float4*>(wp + 4);
        }

        // ---- compute on current buffer ----
        #pragma unroll
        for (int s = 0; s < 2; s++) {
            const int k8 = s * 8;
            unsigned af[2][4], bf[8][2];
            #pragma unroll
            for (int t = 0; t < 2; t++) {
                const int m0 = wm + t * 16 + g;
                af[t][0] = As[buf][k8 + q    ][m0];
                af[t][1] = As[buf][k8 + q    ][m0 + 8];
                af[t][2] = As[buf][k8 + q + 4][m0];
                af[t][3] = As[buf][k8 + q + 4][m0 + 8];
            }
            #pragma unroll
            for (int j = 0; j < 8; j++) {
                const int n0 = wn + j * 8 + g;
                bf[j][0] = Bs[buf][k8 + q    ][n0];
                bf[j][1] = Bs[buf][k8 + q + 4][n0];
            }
            #pragma unroll
            for (int t = 0; t < 2; t++)
                #pragma unroll
                for (int j = 0; j < 8; j++)
                    mma16n8k8(acc[t][j], af[t], bf[j]);
        }

        // ---- store prefetched tile into the other buffer ----
        if (more) {
            const int nb = buf ^ 1;
            As[nb][acol0 + 0][arow] = f2tf32(na0.x);
            As[nb][acol0 + 1][arow] = f2tf32(na0.y);
            As[nb][acol0 + 2][arow] = f2tf32(na0.z);
            As[nb][acol0 + 3][arow] = f2tf32(na0.w);
            As[nb][acol0 + 4][arow] = f2tf32(na1.x);
            As[nb][acol0 + 5][arow] = f2tf32(na1.y);
            As[nb][acol0 + 6][arow] = f2tf32(na1.z);
            As[nb][acol0 + 7][arow] = f2tf32(na1.w);
            uint4 u0, u1;
            u0.x = f2tf32(nb0.x); u0.y = f2tf32(nb0.y);
            u0.z = f2tf32(nb0.z); u0.w = f2tf32(nb0.w);
            u1.x = f2tf32(nb1.x); u1.y = f2tf32(nb1.y);
            u1.z = f2tf32(nb1.z); u1.w = f2tf32(nb1.w);
            *reinterpret_cast<uint4*>(&Bs[nb][brow][bcol0])     = u0;
            *reinterpret_cast<uint4*>(&Bs[nb][brow][bcol0 + 4]) = u1;
        }
        __syncthreads();
        buf ^= 1;
    }

    // ---- epilogue ----
    #pragma unroll
    for (int t = 0; t < 2; t++) {
        const int m0 = bm0 + wm + t * 16 + g;
        const int m1 = m0 + 8;
        #pragma unroll
        for (int j = 0; j < 8; j++) {
            const int n0 = bn0 + wn + j * 8 + q * 2;
            const float b0 = bias[n0], b1 = bias[n0 + 1];
            float v00 = acc[t][j][0] + b0;
            float v01 = acc[t][j][1] + b1;
            float v10 = acc[t][j][2] + b0;
            float v11 = acc[t][j][3] + b1;
            if (MODE == EP_BIAS_GELU) {
                v00 = 0.5f * v00 * (1.f + erff(v00 * 0.70710678118654752f));
                v01 = 0.5f * v01 * (1.f + erff(v01 * 0.70710678118654752f));
                v10 = 0.5f * v10 * (1.f + erff(v10 * 0.70710678118654752f));
                v11 = 0.5f * v11 * (1.f + erff(v11 * 0.70710678118654752f));
            }
            if (MODE == EP_BIAS_RES) {
                const float2 r0 = *reinterpret_cast<const float2*>(R + (size_t)m0 * N + n0);
                const float2 r1 = *reinterpret_cast<const float2*>(R + (size_t)m1 * N + n0);
                v00 += r0.x; v01 += r0.y; v10 += r1.x; v11 += r1.y;
            }
            *reinterpret_cast<float2*>(C + (size_t)m0 * N + n0) = make_float2(v00, v01);
            *reinterpret_cast<float2*>(C + (size_t)m1 * N + n0) = make_float2(v10, v11);
        }
    }
}

// ---------------------------------------------------------------------------
// graph-token fill
// ---------------------------------------------------------------------------
__global__ void fill_token_kernel(const float* __restrict__ gt, float* __restrict__ h)
{
    h[(size_t)blockIdx.x * NTOT * HID + threadIdx.x] = gt[threadIdx.x];
}

// ---------------------------------------------------------------------------
// Structural bias precompute
// ---------------------------------------------------------------------------
__global__ void bias_kernel(const int* __restrict__ len_spd,
                            const float* __restrict__ spd_emb,
                            const float* __restrict__ virt,
                            float* __restrict__ bias)
{
    const size_t idx = (size_t)blockIdx.x * blockDim.x + threadIdx.x;
    const size_t total = (size_t)BATCH * NHEAD * NTOT * NTOT;
    if (idx >= total) return;
    const int j = (int)(idx & 255);
    const int i = (int)((idx >> 8) & 255);
    const int h = (int)((idx >> 16) % NHEAD);
    const int b = (int)(idx / ((size_t)NHEAD * NTOT * NTOT));
    float v;
    if (i == 0 || j == 0) {
        v = virt[h];
    } else {
        const int lsp = len_spd[((size_t)b * NTOK + (i - 1)) * NTOK + (j - 1)];
        v = (lsp == 0) ? 0.f : spd_emb[lsp * NHEAD + h];
    }
    bias[idx] = v;
}

// ---------------------------------------------------------------------------
// LayerNorm
// ---------------------------------------------------------------------------
__global__ __launch_bounds__(256) void ln_kernel(
    const float* __restrict__ X, const float* __restrict__ w,
    const float* __restrict__ b, float* __restrict__ Y)
{
    const int row = blockIdx.x;
    const float* x = X + (size_t)row * HID;
    float* y = Y + (size_t)row * HID;
    const int tid = threadIdx.x;

    float v0 = x[tid], v1 = x[tid + 256], v2 = x[tid + 512];
    float s = v0 + v1 + v2;

    __shared__ float red[8];
    #pragma unroll
    for (int o = 16; o > 0; o >>= 1) s += __shfl_xor_sync(~0u, s, o);
    if ((tid & 31) == 0) red[tid >> 5] = s;
    __syncthreads();
    float tot = red[0];
    #pragma unroll
    for (int wv = 1; wv < 8; wv++) tot += red[wv];
    const float mu = tot * (1.f / HID);
    __syncthreads();

    const float d0 = v0 - mu, d1 = v1 - mu, d2 = v2 - mu;
    float s2 = d0 * d0 + d1 * d1 + d2 * d2;
    #pragma unroll
    for (int o = 16; o > 0; o >>= 1) s2 += __shfl_xor_sync(~0u, s2, o);
    if ((tid & 31) == 0) red[tid >> 5] = s2;
    __syncthreads();
    float var = red[0];
    #pragma unroll
    for (int wv = 1; wv < 8; wv++) var += red[wv];
    var *= (1.f / HID);
    const float inv = rsqrtf(var + 1e-5f);

    y[tid]       = d0 * inv * w[tid]       + b[tid];
    y[tid + 256] = d1 * inv * w[tid + 256] + b[tid + 256];
    y[tid + 512] = d2 * inv * w[tid + 512] + b[tid + 512];
}

// ---------------------------------------------------------------------------
// Attention (unchanged this round)
// ---------------------------------------------------------------------------
#define KVSTRIDE 65
#define ATTN_SMEM ((2 * 256 * KVSTRIDE + 64 + 256 + 256 + 16) * sizeof(float))

__global__ __launch_bounds__(256) void attn_kernel(
    const float* __restrict__ Q, const float* __restrict__ K,
    const float* __restrict__ V, const float* __restrict__ bias,
    float* __restrict__ O)
{
    extern __shared__ float sm[];
    float* Ks   = sm;
    float* Vs   = Ks + 256 * KVSTRIDE;
    float* qs   = Vs + 256 * KVSTRIDE;
    float* pp   = qs + 64;
    float* part = pp + 256;
    float* redm = part + 256;
    float* reds = redm + 8;

    const int h = blockIdx.x;
    const int b = blockIdx.y;
    const int tid = threadIdx.x;
    const int lane = tid & 31;
    const int warp = tid >> 5;

    const size_t base = (size_t)b * NTOT * HID + (size_t)h * HDIM;

    for (int idx = tid; idx < 256 * 64; idx += 256) {
        const int j = idx >> 6, dd = idx & 63;
        Ks[j * KVSTRIDE + dd] = K[base + (size_t)j * HID + dd];
        Vs[j * KVSTRIDE + dd] = V[base + (size_t)j * HID + dd];
    }
    __syncthreads();

    const float* brow = bias + (((size_t)b * NHEAD + h) * NTOT) * NTOT;

    for (int i = 0; i < NTOT; i++) {
        if (tid < 64) qs[tid] = Q[base + (size_t)i * HID + tid];
        __syncthreads();

        float s = 0.f;
        const float* kr = &Ks[tid * KVSTRIDE];
        #pragma unroll 16
        for (int dd = 0; dd < 64; dd++) s = fmaf(qs[dd], kr[dd], s);
        s = s * 0.125f + brow[(size_t)i * NTOT + tid];

        float m = s;
        #pragma unroll
        for (int o = 16; o > 0; o >>= 1) m = fmaxf(m, __shfl_xor_sync(~0u, m, o));
        if (lane == 0) redm[warp] = m;
        __syncthreads();
        float mall = redm[0];
        #pragma unroll
        for (int wv = 1; wv < 8; wv++) mall = fmaxf(mall, redm[wv]);

        const float e = expf(s - mall);
        pp[tid] = e;
        float se = e;
        #pragma unroll
        for (int o = 16; o > 0; o >>= 1) se += __shfl_xor_sync(~0u, se, o);
        if (lane == 0) reds[warp] = se;
        __syncthreads();
        float sum = reds[0];
        #pragma unroll
        for (int wv = 1; wv < 8; wv++) sum += reds[wv];
        const float invsum = 1.f / sum;

        const int gg = tid >> 6, dd = tid & 63;
        float acc = 0.f;
        #pragma unroll 16
        for (int jj = 0; jj < 64; jj++) {
            const int jr = gg * 64 + jj;
            acc = fmaf(pp[jr], Vs[jr * KVSTRIDE + dd], acc);
        }
        part[tid] = acc;
        __syncthreads();

        if (tid < 64) {
            const float o4 = (part[tid] + part[64 + tid] + part[128 + tid] + part[192 + tid]) * invsum;
            O[base + (size_t)i * HID + tid] = o4;
        }
        __syncthreads();
    }
}

// ---------------------------------------------------------------------------
// Launch
// ---------------------------------------------------------------------------
extern "C" void kernel_launch(void* const* d_in, const int* in_sizes, int n_in,
                              void* d_out, int out_size)
{
    const float* x          = (const float*)d_in[0];
    const int*   len_spd    = (const int*)  d_in[1];
    const float* atom_W     = (const float*)d_in[2];
    const float* atom_b     = (const float*)d_in[3];
    const float* spd_emb    = (const float*)d_in[4];
    const float* graph_tok  = (const float*)d_in[5];
    const float* virt_dist  = (const float*)d_in[6];
    const float* ln1_w      = (const float*)d_in[7];
    const float* ln1_b      = (const float*)d_in[8];
    const float* Wq         = (const float*)d_in[9];
    const float* bq         = (const float*)d_in[10];
    const float* Wk         = (const float*)d_in[11];
    const float* bk         = (const float*)d_in[12];
    const float* Wv         = (const float*)d_in[13];
    const float* bv         = (const float*)d_in[14];
    const float* Wo         = (const float*)d_in[15];
    const float* bo         = (const float*)d_in[16];
    const float* ln2_w      = (const float*)d_in[17];
    const float* ln2_b      = (const float*)d_in[18];
    const float* W1         = (const float*)d_in[19];
    const float* b1         = (const float*)d_in[20];
    const float* W2         = (const float*)d_in[21];
    const float* b2         = (const float*)d_in[22];
    const float* fln_w      = (const float*)d_in[23];
    const float* fln_b      = (const float*)d_in[24];

    float *h, *y, *q, *k, *v, *o, *f, *bias;
    cudaGetSymbolAddress((void**)&h,    g_h);
    cudaGetSymbolAddress((void**)&y,    g_y);
    cudaGetSymbolAddress((void**)&q,    g_q);
    cudaGetSymbolAddress((void**)&k,    g_k);
    cudaGetSymbolAddress((void**)&v,    g_v);
    cudaGetSymbolAddress((void**)&o,    g_o);
    cudaGetSymbolAddress((void**)&f,    g_f);
    cudaGetSymbolAddress((void**)&bias, g_bias);

    cudaFuncSetAttribute(attn_kernel, cudaFuncAttributeMaxDynamicSharedMemorySize,
                         (int)ATTN_SMEM);

    // 1) atom encoder (fp32, K=64, remapped rows)
    {
        dim3 grid(HID / BN, (MATOM + BM - 1) / BM);
        sgemm_kernel<EP_BIAS, true><<<grid, 256>>>(x, atom_W, atom_b, nullptr, h,
                                                   MATOM, DIN, HID);
    }
    // 2) graph token row 0 per batch
    fill_token_kernel<<<BATCH, HID>>>(graph_tok, h);

    // 3) structural bias (once)
    {
        const size_t total = (size_t)BATCH * NHEAD * NTOT * NTOT;
        bias_kernel<<<(unsigned)((total + 255) / 256), 256>>>(len_spd, spd_emb,
                                                              virt_dist, bias);
    }

    const dim3 gHID(HID / XBN, MROWS / XBM);   // 6 x 64
    const dim3 gFFN(FFN / XBN, MROWS / XBM);   // 24 x 64

    for (int l = 0; l < NLAYER; l++) {
        const size_t wofs  = (size_t)l * HID * HID;
        const size_t bofs  = (size_t)l * HID;
        const size_t w1ofs = (size_t)l * HID * FFN;
        const size_t b1ofs = (size_t)l * FFN;
        const size_t w2ofs = (size_t)l * FFN * HID;

        ln_kernel<<<MROWS, 256>>>(h, ln1_w + bofs, ln1_b + bofs, y);

        tgemm_kernel<EP_BIAS><<<gHID, 256>>>(y, Wq + wofs, bq + bofs, nullptr, q,
                                             MROWS, HID, HID);
        tgemm_kernel<EP_BIAS><<<gHID, 256>>>(y, Wk + wofs, bk + bofs, nullptr, k,
                                             MROWS, HID, HID);
        tgemm_kernel<EP_BIAS><<<gHID, 256>>>(y, Wv + wofs, bv + bofs, nullptr, v,
                                             MROWS, HID, HID);

        attn_kernel<<<dim3(NHEAD, BATCH), 256, ATTN_SMEM>>>(q, k, v, bias, o);

        tgemm_kernel<EP_BIAS_RES><<<gHID, 256>>>(o, Wo + wofs, bo + bofs, h, h,
                                                 MROWS, HID, HID);

        ln_kernel<<<MROWS, 256>>>(h, ln2_w + bofs, ln2_b + bofs, y);

        tgemm_kernel<EP_BIAS_GELU><<<gFFN, 256>>>(y, W1 + w1ofs, b1 + b1ofs,
                                                  nullptr, f, MROWS, HID, FFN);
        tgemm_kernel<EP_BIAS_RES><<<gHID, 256>>>(f, W2 + w2ofs, b2 + bofs, h, h,
                                                 MROWS, FFN, HID);
    }

    ln_kernel<<<MROWS, 256>>>(h, fln_w, fln_b, (float*)d_out);
}

// round 5
// speedup vs baseline: 1.6361x; 1.6361x over previous
#include <cuda_runtime.h>
#include <cuda_bf16.h>
#include <math.h>

// ---------------------------------------------------------------------------
// Problem constants
// ---------------------------------------------------------------------------
#define BATCH   32
#define NTOK    255
#define NTOT    256
#define DIN     64
#define NHEAD   12
#define HID     768
#define FFN     3072
#define NLAYER  6
#define HDIM    64
#define MROWS   (BATCH*NTOT) // 8192
#define MATOM   (BATCH*NTOK) // 8160

// ---------------------------------------------------------------------------
// Scratch (device globals; no allocations allowed)
// ---------------------------------------------------------------------------
__device__ __align__(256) float g_h  [(size_t)MROWS*HID];
__device__ __align__(256) float g_y  [(size_t)MROWS*HID];
__device__ __align__(256) float g_q  [(size_t)MROWS*HID];
__device__ __align__(256) float g_k  [(size_t)MROWS*HID];
__device__ __align__(256) float g_v  [(size_t)MROWS*HID];
__device__ __align__(256) float g_o  [(size_t)MROWS*HID];
__device__ __align__(256) float g_f  [(size_t)MROWS*FFN];
__device__ __align__(256) float g_bias[(size_t)BATCH*NHEAD*NTOT*NTOT];

enum { EP_BIAS = 0, EP_BIAS_RES = 1, EP_BIAS_GELU = 2 };

// ---------------------------------------------------------------------------
// fp32 SGEMM (atom-encoder only: K=64, row remap)
// ---------------------------------------------------------------------------
#define BM 128
#define BN 128
#define BK 8
#define TM 8
#define TN 8

template<int MODE, bool REMAP>
__global__ __launch_bounds__(256) void sgemm_kernel(
    const float* __restrict__ A, const float* __restrict__ W,
    const float* __restrict__ bias, const float* __restrict__ R,
    float* __restrict__ C, int M, int K, int N)
{
    __shared__ float As[BK][BM];
    __shared__ float Bs[BK][BN];

    const int tid = threadIdx.x;
    const int bm0 = blockIdx.y * BM;
    const int bn0 = blockIdx.x * BN;
    const int tx = tid & 15;
    const int ty = tid >> 4;

    float acc[TM][TN];
    #pragma unroll
    for (int i = 0; i < TM; i++)
        #pragma unroll
        for (int j = 0; j < TN; j++) acc[i][j] = 0.f;

    const int arow = tid >> 1;
    const int acol = (tid & 1) * 4;
    const int brow = tid >> 5;
    const int bcol = (tid & 31) * 4;

    for (int k0 = 0; k0 < K; k0 += BK) {
        float4 av;
        const int gm = bm0 + arow;
        if (gm < M)
            av = *reinterpret_cast<const float4*>(A + (size_t)gm * K + k0 + acol);
        else
            av = make_float4(0.f, 0.f, 0.f, 0.f);
        As[acol + 0][arow] = av.x;
        As[acol + 1][arow] = av.y;
        As[acol + 2][arow] = av.z;
        As[acol + 3][arow] = av.w;

        const float4 bv = *reinterpret_cast<const float4*>(
            W + (size_t)(k0 + brow) * N + bn0 + bcol);
        *reinterpret_cast<float4*>(&Bs[brow][bcol]) = bv;

        __syncthreads();
        #pragma unroll
        for (int k = 0; k < BK; k++) {
            float af[TM], bf[TN];
            #pragma unroll
            for (int i = 0; i < TM; i++) af[i] = As[k][ty * TM + i];
            #pragma unroll
            for (int j = 0; j < TN; j++) bf[j] = Bs[k][tx * TN + j];
            #pragma unroll
            for (int i = 0; i < TM; i++)
                #pragma unroll
                for (int j = 0; j < TN; j++)
                    acc[i][j] = fmaf(af[i], bf[j], acc[i][j]);
        }
        __syncthreads();
    }

    #pragma unroll
    for (int i = 0; i < TM; i++) {
        const int m = bm0 + ty * TM + i;
        if (m >= M) continue;
        size_t orow;
        if (REMAP) orow = (size_t)m + (size_t)(m / NTOK) * 1 + 1;
        else       orow = (size_t)m;
        #pragma unroll
        for (int j = 0; j < TN; j++) {
            const int nn = bn0 + tx * TN + j;
            float v = acc[i][j] + bias[nn];
            if (MODE == EP_BIAS_GELU)
                v = 0.5f * v * (1.f + erff(v * 0.70710678118654752f));
            if (MODE == EP_BIAS_RES)
                v += R[orow * N + nn];
            C[orow * N + nn] = v;
        }
    }
}

// ---------------------------------------------------------------------------
// TF32 tensor-core GEMM, 2-stage cp.async pipeline, cvt on fragment load.
// CTA tile 128x128x16, 8 warps (4xM, 2xN), warp tile 32x64, m16n8k8.tf32.
// A in smem as [m][k] (k-stride 20 -> conflict-free), B as [k][n] (stride 136).
// ---------------------------------------------------------------------------
#define XBM 128
#define XBN 128
#define XBK 16
#define ALD 20     // A smem k-stride: lanes map to banks g*20+q (all distinct)
#define BLD 136    // B smem n-stride: banks q*8+g (all distinct)

__device__ __forceinline__ unsigned f2tf32(float f) {
    unsigned u;
    asm("cvt.rna.tf32.f32 %0, %1;" : "=r"(u) : "f"(f));
    return u;
}

__device__ __forceinline__ void cp16(void* smem, const void* gmem) {
    unsigned s = (unsigned)__cvta_generic_to_shared(smem);
    asm volatile("cp.async.cg.shared.global [%0], [%1], 16;" :: "r"(s), "l"(gmem));
}

__device__ __forceinline__ void mma16n8k8(float c[4], const unsigned a[4],
                                          const unsigned b[2]) {
    asm volatile(
        "mma.sync.aligned.m16n8k8.row.col.f32.tf32.tf32.f32 "
        "{%0,%1,%2,%3}, {%4,%5,%6,%7}, {%8,%9}, {%0,%1,%2,%3};"
        : "+f"(c[0]), "+f"(c[1]), "+f"(c[2]), "+f"(c[3])
        : "r"(a[0]), "r"(a[1]), "r"(a[2]), "r"(a[3]), "r"(b[0]), "r"(b[1]));
}

template<int MODE>
__global__ __launch_bounds__(256, 2) void tgemm_kernel(
    const float* __restrict__ A, const float* __restrict__ W,
    const float* __restrict__ bias, const float* __restrict__ R,
    float* __restrict__ C, int M, int K, int N)
{
    __shared__ float As[2][XBM][ALD];   // 20480 B
    __shared__ float Bs[2][XBK][BLD];   // 17408 B

    const int tid  = threadIdx.x;
    const int lane = tid & 31;
    const int warp = tid >> 5;
    const int g    = lane >> 2;   // 0..7
    const int q    = lane & 3;    // 0..3

    const int bm0 = blockIdx.y * XBM;
    const int bn0 = blockIdx.x * XBN;
    const int wm  = (warp >> 1) * 32;
    const int wn  = (warp & 1) * 64;

    // A loader: chunks c = tid, tid+256 of 512; row = c>>2, kc = (c&3)*4
    const int ar0 = tid >> 2;            // 0..63
    const int akc = (tid & 3) * 4;       // 0,4,8,12
    // B loader: row = c>>5, nc = (c&31)*4
    const int br0 = tid >> 5;            // 0..7
    const int bnc = (tid & 31) * 4;      // 0..124

    const float* Abase = A + (size_t)bm0 * K;
    const float* Wbase = W + bn0;

    float acc[2][8][4];
    #pragma unroll
    for (int t = 0; t < 2; t++)
        #pragma unroll
        for (int j = 0; j < 8; j++)
            #pragma unroll
            for (int r = 0; r < 4; r++) acc[t][j][r] = 0.f;

    // issue one K-tile's loads into smem buffer `b`
    auto issue = [&](int b, int k0) {
        cp16(&As[b][ar0     ][akc], Abase + (size_t)(ar0     ) * K + k0 + akc);
        cp16(&As[b][ar0 + 64][akc], Abase + (size_t)(ar0 + 64) * K + k0 + akc);
        cp16(&Bs[b][br0    ][bnc], Wbase + (size_t)(k0 + br0    ) * N + bnc);
        cp16(&Bs[b][br0 + 8][bnc], Wbase + (size_t)(k0 + br0 + 8) * N + bnc);
        asm volatile("cp.async.commit_group;");
    };

    issue(0, 0);

    int buf = 0;
    for (int k0 = 0; k0 < K; k0 += XBK) {
        const bool more = (k0 + XBK) < K;
        if (more) issue(buf ^ 1, k0 + XBK);

        if (more) asm volatile("cp.async.wait_group 1;");
        else      asm volatile("cp.async.wait_group 0;");
        __syncthreads();

        #pragma unroll
        for (int s = 0; s < 2; s++) {
            const int k8 = s * 8;
            unsigned af[2][4], bfr[8][2];
            #pragma unroll
            for (int t = 0; t < 2; t++) {
                const int m0 = wm + t * 16 + g;
                af[t][0] = f2tf32(As[buf][m0    ][k8 + q]);
                af[t][1] = f2tf32(As[buf][m0 + 8][k8 + q]);
                af[t][2] = f2tf32(As[buf][m0    ][k8 + q + 4]);
                af[t][3] = f2tf32(As[buf][m0 + 8][k8 + q + 4]);
            }
            #pragma unroll
            for (int j = 0; j < 8; j++) {
                const int n0 = wn + j * 8 + g;
                bfr[j][0] = f2tf32(Bs[buf][k8 + q    ][n0]);
                bfr[j][1] = f2tf32(Bs[buf][k8 + q + 4][n0]);
            }
            #pragma unroll
            for (int t = 0; t < 2; t++)
                #pragma unroll
                for (int j = 0; j < 8; j++)
                    mma16n8k8(acc[t][j], af[t], bfr[j]);
        }
        __syncthreads();
        buf ^= 1;
    }

    // ---- epilogue ----
    #pragma unroll
    for (int t = 0; t < 2; t++) {
        const int m0 = bm0 + wm + t * 16 + g;
        const int m1 = m0 + 8;
        #pragma unroll
        for (int j = 0; j < 8; j++) {
            const int n0 = bn0 + wn + j * 8 + q * 2;
            const float b0 = bias[n0], b1 = bias[n0 + 1];
            float v00 = acc[t][j][0] + b0;
            float v01 = acc[t][j][1] + b1;
            float v10 = acc[t][j][2] + b0;
            float v11 = acc[t][j][3] + b1;
            if (MODE == EP_BIAS_GELU) {
                v00 = 0.5f * v00 * (1.f + erff(v00 * 0.70710678118654752f));
                v01 = 0.5f * v01 * (1.f + erff(v01 * 0.70710678118654752f));
                v10 = 0.5f * v10 * (1.f + erff(v10 * 0.70710678118654752f));
                v11 = 0.5f * v11 * (1.f + erff(v11 * 0.70710678118654752f));
            }
            if (MODE == EP_BIAS_RES) {
                const float2 r0 = *reinterpret_cast<const float2*>(R + (size_t)m0 * N + n0);
                const float2 r1 = *reinterpret_cast<const float2*>(R + (size_t)m1 * N + n0);
                v00 += r0.x; v01 += r0.y; v10 += r1.x; v11 += r1.y;
            }
            *reinterpret_cast<float2*>(C + (size_t)m0 * N + n0) = make_float2(v00, v01);
            *reinterpret_cast<float2*>(C + (size_t)m1 * N + n0) = make_float2(v10, v11);
        }
    }
}

// ---------------------------------------------------------------------------
// graph-token fill
// ---------------------------------------------------------------------------
__global__ void fill_token_kernel(const float* __restrict__ gt, float* __restrict__ h)
{
    h[(size_t)blockIdx.x * NTOT * HID + threadIdx.x] = gt[threadIdx.x];
}

// ---------------------------------------------------------------------------
// Structural bias precompute
// ---------------------------------------------------------------------------
__global__ void bias_kernel(const int* __restrict__ len_spd,
                            const float* __restrict__ spd_emb,
                            const float* __restrict__ virt,
                            float* __restrict__ bias)
{
    const size_t idx = (size_t)blockIdx.x * blockDim.x + threadIdx.x;
    const size_t total = (size_t)BATCH * NHEAD * NTOT * NTOT;
    if (idx >= total) return;
    const int j = (int)(idx & 255);
    const int i = (int)((idx >> 8) & 255);
    const int h = (int)((idx >> 16) % NHEAD);
    const int b = (int)(idx / ((size_t)NHEAD * NTOT * NTOT));
    float v;
    if (i == 0 || j == 0) {
        v = virt[h];
    } else {
        const int lsp = len_spd[((size_t)b * NTOK + (i - 1)) * NTOK + (j - 1)];
        v = (lsp == 0) ? 0.f : spd_emb[lsp * NHEAD + h];
    }
    bias[idx] = v;
}

// ---------------------------------------------------------------------------
// LayerNorm
// ---------------------------------------------------------------------------
__global__ __launch_bounds__(256) void ln_kernel(
    const float* __restrict__ X, const float* __restrict__ w,
    const float* __restrict__ b, float* __restrict__ Y)
{
    const int row = blockIdx.x;
    const float* x = X + (size_t)row * HID;
    float* y = Y + (size_t)row * HID;
    const int tid = threadIdx.x;

    float v0 = x[tid], v1 = x[tid + 256], v2 = x[tid + 512];
    float s = v0 + v1 + v2;

    __shared__ float red[8];
    #pragma unroll
    for (int o = 16; o > 0; o >>= 1) s += __shfl_xor_sync(~0u, s, o);
    if ((tid & 31) == 0) red[tid >> 5] = s;
    __syncthreads();
    float tot = red[0];
    #pragma unroll
    for (int wv = 1; wv < 8; wv++) tot += red[wv];
    const float mu = tot * (1.f / HID);
    __syncthreads();

    const float d0 = v0 - mu, d1 = v1 - mu, d2 = v2 - mu;
    float s2 = d0 * d0 + d1 * d1 + d2 * d2;
    #pragma unroll
    for (int o = 16; o > 0; o >>= 1) s2 += __shfl_xor_sync(~0u, s2, o);
    if ((tid & 31) == 0) red[tid >> 5] = s2;
    __syncthreads();
    float var = red[0];
    #pragma unroll
    for (int wv = 1; wv < 8; wv++) var += red[wv];
    var *= (1.f / HID);
    const float inv = rsqrtf(var + 1e-5f);

    y[tid]       = d0 * inv * w[tid]       + b[tid];
    y[tid + 256] = d1 * inv * w[tid + 256] + b[tid + 256];
    y[tid + 512] = d2 * inv * w[tid + 512] + b[tid + 512];
}

// ---------------------------------------------------------------------------
// Attention (unchanged)
// ---------------------------------------------------------------------------
#define KVSTRIDE 65
#define ATTN_SMEM ((2 * 256 * KVSTRIDE + 64 + 256 + 256 + 16) * sizeof(float))

__global__ __launch_bounds__(256) void attn_kernel(
    const float* __restrict__ Q, const float* __restrict__ K,
    const float* __restrict__ V, const float* __restrict__ bias,
    float* __restrict__ O)
{
    extern __shared__ float sm[];
    float* Ks   = sm;
    float* Vs   = Ks + 256 * KVSTRIDE;
    float* qs   = Vs + 256 * KVSTRIDE;
    float* pp   = qs + 64;
    float* part = pp + 256;
    float* redm = part + 256;
    float* reds = redm + 8;

    const int h = blockIdx.x;
    const int b = blockIdx.y;
    const int tid = threadIdx.x;
    const int lane = tid & 31;
    const int warp = tid >> 5;

    const size_t base = (size_t)b * NTOT * HID + (size_t)h * HDIM;

    for (int idx = tid; idx < 256 * 64; idx += 256) {
        const int j = idx >> 6, dd = idx & 63;
        Ks[j * KVSTRIDE + dd] = K[base + (size_t)j * HID + dd];
        Vs[j * KVSTRIDE + dd] = V[base + (size_t)j * HID + dd];
    }
    __syncthreads();

    const float* brow = bias + (((size_t)b * NHEAD + h) * NTOT) * NTOT;

    for (int i = 0; i < NTOT; i++) {
        if (tid < 64) qs[tid] = Q[base + (size_t)i * HID + tid];
        __syncthreads();

        float s = 0.f;
        const float* kr = &Ks[tid * KVSTRIDE];
        #pragma unroll 16
        for (int dd = 0; dd < 64; dd++) s = fmaf(qs[dd], kr[dd], s);
        s = s * 0.125f + brow[(size_t)i * NTOT + tid];

        float m = s;
        #pragma unroll
        for (int o = 16; o > 0; o >>= 1) m = fmaxf(m, __shfl_xor_sync(~0u, m, o));
        if (lane == 0) redm[warp] = m;
        __syncthreads();
        float mall = redm[0];
        #pragma unroll
        for (int wv = 1; wv < 8; wv++) mall = fmaxf(mall, redm[wv]);

        const float e = expf(s - mall);
        pp[tid] = e;
        float se = e;
        #pragma unroll
        for (int o = 16; o > 0; o >>= 1) se += __shfl_xor_sync(~0u, se, o);
        if (lane == 0) reds[warp] = se;
        __syncthreads();
        float sum = reds[0];
        #pragma unroll
        for (int wv = 1; wv < 8; wv++) sum += reds[wv];
        const float invsum = 1.f / sum;

        const int gg = tid >> 6, dd = tid & 63;
        float acc = 0.f;
        #pragma unroll 16
        for (int jj = 0; jj < 64; jj++) {
            const int jr = gg * 64 + jj;
            acc = fmaf(pp[jr], Vs[jr * KVSTRIDE + dd], acc);
        }
        part[tid] = acc;
        __syncthreads();

        if (tid < 64) {
            const float o4 = (part[tid] + part[64 + tid] + part[128 + tid] + part[192 + tid]) * invsum;
            O[base + (size_t)i * HID + tid] = o4;
        }
        __syncthreads();
    }
}

// ---------------------------------------------------------------------------
// Launch
// ---------------------------------------------------------------------------
extern "C" void kernel_launch(void* const* d_in, const int* in_sizes, int n_in,
                              void* d_out, int out_size)
{
    const float* x          = (const float*)d_in[0];
    const int*   len_spd    = (const int*)  d_in[1];
    const float* atom_W     = (const float*)d_in[2];
    const float* atom_b     = (const float*)d_in[3];
    const float* spd_emb    = (const float*)d_in[4];
    const float* graph_tok  = (const float*)d_in[5];
    const float* virt_dist  = (const float*)d_in[6];
    const float* ln1_w      = (const float*)d_in[7];
    const float* ln1_b      = (const float*)d_in[8];
    const float* Wq         = (const float*)d_in[9];
    const float* bq         = (const float*)d_in[10];
    const float* Wk         = (const float*)d_in[11];
    const float* bk         = (const float*)d_in[12];
    const float* Wv         = (const float*)d_in[13];
    const float* bv         = (const float*)d_in[14];
    const float* Wo         = (const float*)d_in[15];
    const float* bo         = (const float*)d_in[16];
    const float* ln2_w      = (const float*)d_in[17];
    const float* ln2_b      = (const float*)d_in[18];
    const float* W1         = (const float*)d_in[19];
    const float* b1         = (const float*)d_in[20];
    const float* W2         = (const float*)d_in[21];
    const float* b2         = (const float*)d_in[22];
    const float* fln_w      = (const float*)d_in[23];
    const float* fln_b      = (const float*)d_in[24];

    float *h, *y, *q, *k, *v, *o, *f, *bias;
    cudaGetSymbolAddress((void**)&h,    g_h);
    cudaGetSymbolAddress((void**)&y,    g_y);
    cudaGetSymbolAddress((void**)&q,    g_q);
    cudaGetSymbolAddress((void**)&k,    g_k);
    cudaGetSymbolAddress((void**)&v,    g_v);
    cudaGetSymbolAddress((void**)&o,    g_o);
    cudaGetSymbolAddress((void**)&f,    g_f);
    cudaGetSymbolAddress((void**)&bias, g_bias);

    cudaFuncSetAttribute(attn_kernel, cudaFuncAttributeMaxDynamicSharedMemorySize,
                         (int)ATTN_SMEM);

    // 1) atom encoder (fp32, K=64, remapped rows)
    {
        dim3 grid(HID / BN, (MATOM + BM - 1) / BM);
        sgemm_kernel<EP_BIAS, true><<<grid, 256>>>(x, atom_W, atom_b, nullptr, h,
                                                   MATOM, DIN, HID);
    }
    // 2) graph token row 0 per batch
    fill_token_kernel<<<BATCH, HID>>>(graph_tok, h);

    // 3) structural bias (once)
    {
        const size_t total = (size_t)BATCH * NHEAD * NTOT * NTOT;
        bias_kernel<<<(unsigned)((total + 255) / 256), 256>>>(len_spd, spd_emb,
                                                              virt_dist, bias);
    }

    const dim3 gHID(HID / XBN, MROWS / XBM);   // 6 x 64
    const dim3 gFFN(FFN / XBN, MROWS / XBM);   // 24 x 64

    for (int l = 0; l < NLAYER; l++) {
        const size_t wofs  = (size_t)l * HID * HID;
        const size_t bofs  = (size_t)l * HID;
        const size_t w1ofs = (size_t)l * HID * FFN;
        const size_t b1ofs = (size_t)l * FFN;
        const size_t w2ofs = (size_t)l * FFN * HID;

        ln_kernel<<<MROWS, 256>>>(h, ln1_w + bofs, ln1_b + bofs, y);

        tgemm_kernel<EP_BIAS><<<gHID, 256>>>(y, Wq + wofs, bq + bofs, nullptr, q,
                                             MROWS, HID, HID);
        tgemm_kernel<EP_BIAS><<<gHID, 256>>>(y, Wk + wofs, bk + bofs, nullptr, k,
                                             MROWS, HID, HID);
        tgemm_kernel<EP_BIAS><<<gHID, 256>>>(y, Wv + wofs, bv + bofs, nullptr, v,
                                             MROWS, HID, HID);

        attn_kernel<<<dim3(NHEAD, BATCH), 256, ATTN_SMEM>>>(q, k, v, bias, o);

        tgemm_kernel<EP_BIAS_RES><<<gHID, 256>>>(o, Wo + wofs, bo + bofs, h, h,
                                                 MROWS, HID, HID);

        ln_kernel<<<MROWS, 256>>>(h, ln2_w + bofs, ln2_b + bofs, y);

        tgemm_kernel<EP_BIAS_GELU><<<gFFN, 256>>>(y, W1 + w1ofs, b1 + b1ofs,
                                                  nullptr, f, MROWS, HID, FFN);
        tgemm_kernel<EP_BIAS_RES><<<gHID, 256>>>(f, W2 + w2ofs, b2 + bofs, h, h,
                                                 MROWS, FFN, HID);
    }

    ln_kernel<<<MROWS, 256>>>(h, fln_w, fln_b, (float*)d_out);
}